// round 1
// baseline (speedup 1.0000x reference)
#include <cuda_runtime.h>
#include <math.h>

#define B 256
#define D 128
#define T 512
#define H 256
#define C 10
#define N4 1024   // 4 gates * H

// Scratch (device globals; no runtime allocation allowed)
__device__ float g_gates[134217728];   // [B][T][N4]  fp32  = 512 MB
__device__ float g_hbuf[2][B * H];     // double-buffered hidden state
__device__ float g_cbuf[B * H];        // cell state

__device__ __forceinline__ float sigf(float x) { return 1.0f / (1.0f + expf(-x)); }

// ---------------------------------------------------------------------------
// K1: gate pre-activations.  gates[b][t][g*H+h] = sum_d x[b][d][t]*W_gx[d][h] + bias
// GEMM view: M = B*T (m = b*T + t), N = 1024, K = 128.
// Block: 64m x 64n, 256 threads, 4x4 register tile, K chunked by 64.
// ---------------------------------------------------------------------------
__global__ void proj_kernel(const float* __restrict__ x,
                            const float* __restrict__ Wg, const float* __restrict__ Wi,
                            const float* __restrict__ Wf, const float* __restrict__ Wo,
                            const float* __restrict__ bg, const float* __restrict__ bi,
                            const float* __restrict__ bf, const float* __restrict__ bo)
{
    __shared__ float As[64][64];
    __shared__ float Bs[64][64];

    const int tid = threadIdx.x;          // 256
    const int tn = tid & 15;              // 0..15 (n groups of 4)
    const int tm = tid >> 4;              // 0..15 (m groups of 4)
    const int n0 = blockIdx.x * 64;       // 0..960
    const int m0 = blockIdx.y * 64;       // 0..131008
    const int b  = m0 >> 9;               // m-tile stays inside one batch row (512 % 64 == 0)
    const int t0 = m0 & 511;
    const int gate = n0 >> 8;              // n-tile stays inside one gate (64 | 256)
    const int hb = n0 & 255;

    const float* W    = (gate == 0) ? Wg : (gate == 1) ? Wi : (gate == 2) ? Wf : Wo;
    const float* bias = (gate == 0) ? bg : (gate == 1) ? bi : (gate == 2) ? bf : bo;

    float acc[4][4] = {};

    for (int kc = 0; kc < 128; kc += 64) {
        __syncthreads();
        #pragma unroll
        for (int i = 0; i < 16; i++) {
            int idx = tid + i * 256;       // 0..4095
            int kk = idx >> 6;
            int mm = idx & 63;
            // A[m][k] = x[b*D*T + k*T + t]; contiguous in t (=mm)  -> coalesced
            As[kk][mm] = x[b * (D * T) + (kc + kk) * T + t0 + mm];
            // B[k][n] = W[k*H + hb + nn]; contiguous in nn         -> coalesced
            Bs[kk][mm] = W[(kc + kk) * H + hb + mm];
        }
        __syncthreads();

        #pragma unroll 8
        for (int kk = 0; kk < 64; kk++) {
            float4 av = *reinterpret_cast<const float4*>(&As[kk][tm * 4]);
            float4 bv = *reinterpret_cast<const float4*>(&Bs[kk][tn * 4]);
            float a[4] = {av.x, av.y, av.z, av.w};
            float c[4] = {bv.x, bv.y, bv.z, bv.w};
            #pragma unroll
            for (int mj = 0; mj < 4; mj++) {
                acc[mj][0] += a[mj] * c[0];
                acc[mj][1] += a[mj] * c[1];
                acc[mj][2] += a[mj] * c[2];
                acc[mj][3] += a[mj] * c[3];
            }
        }
    }

    float bv0 = bias[hb + tn * 4 + 0];
    float bv1 = bias[hb + tn * 4 + 1];
    float bv2 = bias[hb + tn * 4 + 2];
    float bv3 = bias[hb + tn * 4 + 3];

    #pragma unroll
    for (int mj = 0; mj < 4; mj++) {
        size_t m = (size_t)(m0 + tm * 4 + mj);
        float4 v = make_float4(acc[mj][0] + bv0, acc[mj][1] + bv1,
                               acc[mj][2] + bv2, acc[mj][3] + bv3);
        *reinterpret_cast<float4*>(&g_gates[m * N4 + n0 + tn * 4]) = v;
    }
}

// ---------------------------------------------------------------------------
// t = 0 step: h_prev = c_prev = 0, so no recurrent GEMM needed.
// ---------------------------------------------------------------------------
__global__ void init_kernel()
{
    int b = blockIdx.x;
    int h = threadIdx.x;
    size_t base = (size_t)b * T * N4;   // t = 0
    float gv = tanhf(g_gates[base + h]);
    float iv = sigf(g_gates[base + 256 + h]);
    float ov = sigf(g_gates[base + 768 + h]);
    float c = gv * iv;
    g_cbuf[b * H + h] = c;
    g_hbuf[0][b * H + h] = tanhf(c) * ov;
}

// ---------------------------------------------------------------------------
// K2: one recurrent step t (1..511).
// Block computes a 32b x 16h tile of the output, all 4 gates together so the
// pointwise LSTM update finishes locally.  128 threads: tx=h-local(16),
// tb=b-group(8), each thread owns 4 b-rows x 1 h x 4 gates.
// ---------------------------------------------------------------------------
__global__ void step_kernel(int t,
                            const float* __restrict__ Wg, const float* __restrict__ Wi,
                            const float* __restrict__ Wf, const float* __restrict__ Wo)
{
    const float* __restrict__ hprev = g_hbuf[(t + 1) & 1];
    float* __restrict__ hnext = g_hbuf[t & 1];

    __shared__ float hs[64][33];        // [kk][b-local], padded (conflict-free STS)
    __shared__ float Ws[4][64][16];     // [gate][kk][h-local]

    const int tid = threadIdx.x;        // 128
    const int tx = tid & 15;            // h-local
    const int tb = tid >> 4;            // 0..7
    const int h0 = blockIdx.x * 16;
    const int b0 = blockIdx.y * 32;

    float acc[4][4] = {};               // [b][gate]

    for (int kc = 0; kc < 256; kc += 64) {
        __syncthreads();
        #pragma unroll
        for (int i = 0; i < 16; i++) {
            int idx = tid + i * 128;    // 0..2047
            int br = idx >> 6;          // b-local 0..31
            int kk = idx & 63;
            hs[kk][br] = hprev[(b0 + br) * H + kc + kk];   // contiguous over kk
        }
        #pragma unroll
        for (int i = 0; i < 8; i++) {
            int idx = tid + i * 128;    // 0..1023
            int kk = idx >> 4;
            int hh = idx & 15;
            int off = (kc + kk) * H + h0 + hh;
            Ws[0][kk][hh] = Wg[off];
            Ws[1][kk][hh] = Wi[off];
            Ws[2][kk][hh] = Wf[off];
            Ws[3][kk][hh] = Wo[off];
        }
        __syncthreads();

        #pragma unroll 4
        for (int kk = 0; kk < 64; kk++) {
            float wg = Ws[0][kk][tx];
            float wi = Ws[1][kk][tx];
            float wf = Ws[2][kk][tx];
            float wo = Ws[3][kk][tx];
            #pragma unroll
            for (int j = 0; j < 4; j++) {
                float hv = hs[kk][tb * 4 + j];
                acc[j][0] += hv * wg;
                acc[j][1] += hv * wi;
                acc[j][2] += hv * wf;
                acc[j][3] += hv * wo;
            }
        }
    }

    const int h = h0 + tx;
    #pragma unroll
    for (int j = 0; j < 4; j++) {
        int b = b0 + tb * 4 + j;
        size_t base = ((size_t)b * T + t) * N4;
        float gv = tanhf(g_gates[base + h]        + acc[j][0]);
        float iv = sigf (g_gates[base + 256 + h]  + acc[j][1]);
        float fv = sigf (g_gates[base + 512 + h]  + acc[j][2]);
        float ov = sigf (g_gates[base + 768 + h]  + acc[j][3]);
        float c = gv * iv + g_cbuf[b * H + h] * fv;
        g_cbuf[b * H + h] = c;
        hnext[b * H + h] = tanhf(c) * ov;
    }
}

// ---------------------------------------------------------------------------
// K3: out[b][c] = h_final[b][:] @ W_ph[:,c] + b_p[c]
// ---------------------------------------------------------------------------
__global__ void final_kernel(const float* __restrict__ Wp,
                             const float* __restrict__ bp,
                             float* __restrict__ out)
{
    __shared__ float hsm[H];
    int b = blockIdx.x;
    hsm[threadIdx.x] = g_hbuf[(T - 1) & 1][b * H + threadIdx.x];
    __syncthreads();
    if (threadIdx.x < C) {
        float acc = bp[threadIdx.x];
        #pragma unroll 8
        for (int k = 0; k < H; k++)
            acc += hsm[k] * Wp[k * C + threadIdx.x];
        out[b * C + threadIdx.x] = acc;
    }
}

// ---------------------------------------------------------------------------
extern "C" void kernel_launch(void* const* d_in, const int* in_sizes, int n_in,
                              void* d_out, int out_size)
{
    const float* x    = (const float*)d_in[0];
    const float* W_gx = (const float*)d_in[1];
    const float* W_ix = (const float*)d_in[2];
    const float* W_fx = (const float*)d_in[3];
    const float* W_ox = (const float*)d_in[4];
    const float* W_gh = (const float*)d_in[5];
    const float* W_ih = (const float*)d_in[6];
    const float* W_fh = (const float*)d_in[7];
    const float* W_oh = (const float*)d_in[8];
    const float* b_g  = (const float*)d_in[9];
    const float* b_i  = (const float*)d_in[10];
    const float* b_f  = (const float*)d_in[11];
    const float* b_o  = (const float*)d_in[12];
    const float* W_ph = (const float*)d_in[13];
    const float* b_p  = (const float*)d_in[14];
    float* out = (float*)d_out;

    // 1) all input-to-gate projections (one GEMM, bias fused)
    proj_kernel<<<dim3(N4 / 64, (B * T) / 64), 256>>>(
        x, W_gx, W_ix, W_fx, W_ox, b_g, b_i, b_f, b_o);

    // 2) t = 0 (h0 = c0 = 0  ->  pointwise only)
    init_kernel<<<B, H>>>();

    // 3) t = 1 .. T-1 recurrent steps
    for (int t = 1; t < T; t++)
        step_kernel<<<dim3(H / 16, B / 32), 128>>>(t, W_gh, W_ih, W_fh, W_oh);

    // 4) output head
    final_kernel<<<B, H>>>(W_ph, b_p, out);
}

// round 2
// speedup vs baseline: 2.3281x; 2.3281x over previous
#include <cuda_runtime.h>
#include <math.h>

#define B 256
#define D 128
#define T 512
#define H 256
#define C 10
#define N4 1024
#define NCTA 128

// device scratch (no runtime allocation allowed)
__device__ float g_gates[(size_t)B * T * N4];   // [b][t][4H]  512 MB
__device__ float g_hbuf[2][B * H];              // hidden double buffer
__device__ unsigned g_bar;                      // grid barrier counter

__device__ __forceinline__ float sigf(float x) { return 1.0f / (1.0f + expf(-x)); }

__global__ void reset_kernel() { g_bar = 0u; }

// ---------------------------------------------------------------------------
// Proj GEMM: gates[b][t][g*H+h] = sum_d x[b][d][t] * W_gx[d][h] + bias
// M = B*T (m = b*T + t), N = 1024, K = 128.  128x128 tile, 8x8 per thread.
// ---------------------------------------------------------------------------
__global__ __launch_bounds__(256, 2) void proj_kernel(
    const float* __restrict__ x,
    const float* __restrict__ Wg, const float* __restrict__ Wi,
    const float* __restrict__ Wf, const float* __restrict__ Wo,
    const float* __restrict__ bg, const float* __restrict__ bi,
    const float* __restrict__ bf, const float* __restrict__ bo)
{
    __shared__ float As[32][128];
    __shared__ float Bs[32][128];

    const int tid = threadIdx.x;     // 256
    const int tn8 = tid & 15;        // n group (8 each)
    const int tmg = tid >> 4;        // m group (8 each)
    const int n0 = blockIdx.x * 128; // 0..896 (within one gate: 128 | 256)
    const int m0 = blockIdx.y * 128; // within one batch row (128 | 512)
    const int b  = m0 >> 9;
    const int t0 = m0 & 511;
    const int gate = n0 >> 8;
    const int hb = n0 & 255;

    const float* W    = (gate == 0) ? Wg : (gate == 1) ? Wi : (gate == 2) ? Wf : Wo;
    const float* bias = (gate == 0) ? bg : (gate == 1) ? bi : (gate == 2) ? bf : bo;

    float acc[8][8] = {};

    for (int kc = 0; kc < 128; kc += 32) {
        __syncthreads();
        #pragma unroll
        for (int i = 0; i < 4; i++) {
            int q = tid + i * 256;      // 0..1023 float4 slots
            int kk = q >> 5;
            int mq = q & 31;
            *reinterpret_cast<float4*>(&As[kk][mq * 4]) =
                *reinterpret_cast<const float4*>(&x[(size_t)b * (D * T) + (kc + kk) * T + t0 + mq * 4]);
            *reinterpret_cast<float4*>(&Bs[kk][mq * 4]) =
                *reinterpret_cast<const float4*>(&W[(kc + kk) * H + hb + mq * 4]);
        }
        __syncthreads();

        #pragma unroll
        for (int kk = 0; kk < 32; kk++) {
            float a[8], bb[8];
            *reinterpret_cast<float4*>(&a[0]) = *reinterpret_cast<float4*>(&As[kk][tmg * 8]);
            *reinterpret_cast<float4*>(&a[4]) = *reinterpret_cast<float4*>(&As[kk][tmg * 8 + 4]);
            *reinterpret_cast<float4*>(&bb[0]) = *reinterpret_cast<float4*>(&Bs[kk][tn8 * 8]);
            *reinterpret_cast<float4*>(&bb[4]) = *reinterpret_cast<float4*>(&Bs[kk][tn8 * 8 + 4]);
            #pragma unroll
            for (int mi = 0; mi < 8; mi++)
                #pragma unroll
                for (int ni = 0; ni < 8; ni++)
                    acc[mi][ni] += a[mi] * bb[ni];
        }
    }

    float bv[8];
    #pragma unroll
    for (int ni = 0; ni < 8; ni++) bv[ni] = bias[hb + tn8 * 8 + ni];

    #pragma unroll
    for (int mi = 0; mi < 8; mi++) {
        size_t m = (size_t)(m0 + tmg * 8 + mi);
        float4 v0 = make_float4(acc[mi][0] + bv[0], acc[mi][1] + bv[1],
                                acc[mi][2] + bv[2], acc[mi][3] + bv[3]);
        float4 v1 = make_float4(acc[mi][4] + bv[4], acc[mi][5] + bv[5],
                                acc[mi][6] + bv[6], acc[mi][7] + bv[7]);
        *reinterpret_cast<float4*>(&g_gates[m * N4 + n0 + tn8 * 8])     = v0;
        *reinterpret_cast<float4*>(&g_gates[m * N4 + n0 + tn8 * 8 + 4]) = v1;
    }
}

// ---------------------------------------------------------------------------
// Persistent LSTM recurrence.  Grid (32 h-tiles, 4 b-tiles) = 128 CTAs, all
// co-resident.  Each CTA: output slice 64b x 8h x 4 gates.  W slice in smem
// (float4 [k][hl] packing all 4 gates), c in registers, h via global double
// buffer with .cg + grid barrier per step.
// Thread map (256): tx = tid&7 (h-local), tb = tid>>3 (0..31, 2 b each).
// ---------------------------------------------------------------------------
#define HSROW 66
#define SMEM_LSTM (32768 + 2 * 64 * HSROW * 4)

__global__ __launch_bounds__(256, 1) void lstm_kernel(
    const float* __restrict__ Wg, const float* __restrict__ Wi,
    const float* __restrict__ Wf, const float* __restrict__ Wo)
{
    extern __shared__ char smem_raw[];
    float4* ws4 = reinterpret_cast<float4*>(smem_raw);              // [256][8] gates-packed
    float*  hs  = reinterpret_cast<float*>(smem_raw + 32768);       // [2][64][HSROW]
#define HS(s, k, bb) hs[(((s) * 64 + (k)) * HSROW) + (bb)]

    const int tid = threadIdx.x;
    const int tx = tid & 7;
    const int tb = tid >> 3;
    const int h0 = blockIdx.x * 8;
    const int b0 = blockIdx.y * 64;
    const int hh = h0 + tx;

    // Load W slice once: ws4[k*8+hl] = (Wg,Wi,Wf,Wo)[k][h0+hl]
    for (int idx = tid; idx < 2048; idx += 256) {
        int k = idx >> 3, hl = idx & 7;
        int off = k * H + h0 + hl;
        ws4[idx] = make_float4(Wg[off], Wi[off], Wf[off], Wo[off]);
    }
    __syncthreads();

    float cst[2] = {0.f, 0.f};

    for (int t = 0; t < T; t++) {
        const float* rbuf = g_hbuf[(t + 1) & 1];
        float* wbuf = g_hbuf[t & 1];

        // prefetch gate pre-activations (DRAM latency hides behind GEMM)
        float pre[2][4];
        #pragma unroll
        for (int j = 0; j < 2; j++) {
            size_t base = ((size_t)(b0 + tb * 2 + j) * T + t) * N4 + hh;
            pre[j][0] = __ldcg(&g_gates[base]);
            pre[j][1] = __ldcg(&g_gates[base + 256]);
            pre[j][2] = __ldcg(&g_gates[base + 512]);
            pre[j][3] = __ldcg(&g_gates[base + 768]);
        }

        float acc[2][4] = {};
        if (t > 0) {
            float4 r[4];
            #pragma unroll
            for (int i = 0; i < 4; i++) {
                int q = tid + i * 256;
                int bi = q >> 4, kq = q & 15;
                r[i] = __ldcg(reinterpret_cast<const float4*>(&rbuf[(b0 + bi) * H + kq * 4]));
            }
            #pragma unroll
            for (int c = 0; c < 4; c++) {
                const int s = c & 1;
                #pragma unroll
                for (int i = 0; i < 4; i++) {
                    int q = tid + i * 256;
                    int bi = q >> 4, kq = q & 15;
                    HS(s, kq * 4 + 0, bi) = r[i].x;
                    HS(s, kq * 4 + 1, bi) = r[i].y;
                    HS(s, kq * 4 + 2, bi) = r[i].z;
                    HS(s, kq * 4 + 3, bi) = r[i].w;
                }
                if (c < 3) {
                    int kc = (c + 1) * 64;
                    #pragma unroll
                    for (int i = 0; i < 4; i++) {
                        int q = tid + i * 256;
                        int bi = q >> 4, kq = q & 15;
                        r[i] = __ldcg(reinterpret_cast<const float4*>(&rbuf[(b0 + bi) * H + kc + kq * 4]));
                    }
                }
                __syncthreads();
                const float4* wrow = &ws4[(c * 64) * 8 + tx];
                #pragma unroll
                for (int kk = 0; kk < 64; kk++) {
                    float2 hv = *reinterpret_cast<const float2*>(&HS(s, kk, tb * 2));
                    float4 wv = wrow[kk * 8];
                    acc[0][0] += hv.x * wv.x; acc[0][1] += hv.x * wv.y;
                    acc[0][2] += hv.x * wv.z; acc[0][3] += hv.x * wv.w;
                    acc[1][0] += hv.y * wv.x; acc[1][1] += hv.y * wv.y;
                    acc[1][2] += hv.y * wv.z; acc[1][3] += hv.y * wv.w;
                }
                __syncthreads();
            }
        }

        // pointwise LSTM update (c in registers), write h
        #pragma unroll
        for (int j = 0; j < 2; j++) {
            int bgl = b0 + tb * 2 + j;
            float gv = tanhf(pre[j][0] + acc[j][0]);
            float iv = sigf (pre[j][1] + acc[j][1]);
            float fv = sigf (pre[j][2] + acc[j][2]);
            float ov = sigf (pre[j][3] + acc[j][3]);
            float cc = gv * iv + cst[j] * fv;
            cst[j] = cc;
            __stcg(&wbuf[bgl * H + hh], tanhf(cc) * ov);
        }

        // grid barrier (monotonic counter; all 128 CTAs co-resident)
        __syncthreads();
        if (tid == 0) {
            __threadfence();
            atomicAdd(&g_bar, 1u);
            unsigned need = (unsigned)NCTA * (unsigned)(t + 1);
            while (*(volatile unsigned*)&g_bar < need) __nanosleep(64);
        }
        __syncthreads();
    }
#undef HS
}

// ---------------------------------------------------------------------------
// Head: out[b][c] = h_final[b][:] @ W_ph[:,c] + b_p[c]
// ---------------------------------------------------------------------------
__global__ void final_kernel(const float* __restrict__ Wp,
                             const float* __restrict__ bp,
                             float* __restrict__ out)
{
    __shared__ float hsm[H];
    int b = blockIdx.x;
    hsm[threadIdx.x] = g_hbuf[(T - 1) & 1][b * H + threadIdx.x];
    __syncthreads();
    if (threadIdx.x < C) {
        float acc = bp[threadIdx.x];
        #pragma unroll 8
        for (int k = 0; k < H; k++)
            acc += hsm[k] * Wp[k * C + threadIdx.x];
        out[b * C + threadIdx.x] = acc;
    }
}

// ---------------------------------------------------------------------------
extern "C" void kernel_launch(void* const* d_in, const int* in_sizes, int n_in,
                              void* d_out, int out_size)
{
    const float* x    = (const float*)d_in[0];
    const float* W_gx = (const float*)d_in[1];
    const float* W_ix = (const float*)d_in[2];
    const float* W_fx = (const float*)d_in[3];
    const float* W_ox = (const float*)d_in[4];
    const float* W_gh = (const float*)d_in[5];
    const float* W_ih = (const float*)d_in[6];
    const float* W_fh = (const float*)d_in[7];
    const float* W_oh = (const float*)d_in[8];
    const float* b_g  = (const float*)d_in[9];
    const float* b_i  = (const float*)d_in[10];
    const float* b_f  = (const float*)d_in[11];
    const float* b_o  = (const float*)d_in[12];
    const float* W_ph = (const float*)d_in[13];
    const float* b_p  = (const float*)d_in[14];
    float* out = (float*)d_out;

    static bool attr_set = false;
    if (!attr_set) {
        cudaFuncSetAttribute(lstm_kernel,
                             cudaFuncAttributeMaxDynamicSharedMemorySize, SMEM_LSTM);
        attr_set = true;
    }

    reset_kernel<<<1, 1>>>();

    proj_kernel<<<dim3(N4 / 128, (B * T) / 128), 256>>>(
        x, W_gx, W_ix, W_fx, W_ox, b_g, b_i, b_f, b_o);

    lstm_kernel<<<dim3(H / 8, B / 64), 256, SMEM_LSTM>>>(W_gh, W_ih, W_fh, W_oh);

    final_kernel<<<B, H>>>(W_ph, b_p, out);
}